// round 1
// baseline (speedup 1.0000x reference)
#include <cuda_runtime.h>
#include <math.h>
#include <stdint.h>

#define BB 32
#define NN 4096

// ---------------- static device scratch (no allocations allowed) ----------------
__device__ float4 g_pts1[BB*NN];
__device__ float4 g_pts2[BB*512];
__device__ int    g_fidx1[BB*512];
__device__ float  g_nxyz1[BB*512*3];
__device__ int    g_idx1[BB*512*32];
__device__ int    g_fidx2[BB*128];
__device__ float  g_nxyz2[BB*128*3];
__device__ int    g_idx2[BB*128*64];
__device__ float  g_feat1[BB*512*128];
__device__ float  g_feat2[BB*128*256];
__device__ float  g_feat3[BB*1024];
__device__ float  g_fc1o[BB*512];
__device__ float  g_fc2o[BB*256];
__device__ float  g_logits[BB*64];
__device__ float  g_bufA[67108864];   // 256 MiB ping
__device__ float  g_bufB[67108864];   // 256 MiB pong

// no-FMA fp32 helpers (must match XLA's elementwise mul/add ordering)
__device__ __forceinline__ float fm(float a, float b){ return __fmul_rn(a,b); }
__device__ __forceinline__ float fa(float a, float b){ return __fadd_rn(a,b); }

// ---------------- pack xyz + sumsq into float4 for ball query ----------------
__global__ void prep_pts_kernel(const float* __restrict__ xyz, float4* __restrict__ pts, int total){
    int i = blockIdx.x*blockDim.x + threadIdx.x;
    if (i >= total) return;
    float x = xyz[i*3+0], y = xyz[i*3+1], z = xyz[i*3+2];
    pts[i] = make_float4(x, y, z, fa(fa(fm(x,x), fm(y,y)), fm(z,z)));
}

// ---------------- farthest point sampling: one block per batch ----------------
// Replicates jax.lax.scan semantics: fidx[t] = last; mind = min(mind, d(xyz[last]));
// last = argmax(mind) with ties -> lowest index.
template<int PPT>
__global__ void fps_kernel(const float* __restrict__ xyz, int n, int m,
                           int* __restrict__ fidx, float* __restrict__ nxyz){
    const int T = 512;
    int b = blockIdx.x, tid = threadIdx.x;
    const float* p = xyz + (size_t)b*n*3;
    float px[PPT], py[PPT], pz[PPT], mind[PPT];
    #pragma unroll
    for (int i=0;i<PPT;i++){
        int j = tid + i*T;
        if (j < n){ px[i]=p[j*3]; py[i]=p[j*3+1]; pz[i]=p[j*3+2]; mind[i]=1e10f; }
        else mind[i] = -1e30f;
    }
    __shared__ float sv[16];
    __shared__ int   si[16];
    __shared__ float cur[3];
    __shared__ int   slast;
    int last = 0;
    for (int t=0;t<m;t++){
        if (tid == 0){
            fidx[b*m+t] = last;
            float cx=p[last*3], cy=p[last*3+1], cz=p[last*3+2];
            cur[0]=cx; cur[1]=cy; cur[2]=cz;
            nxyz[((size_t)b*m+t)*3+0]=cx;
            nxyz[((size_t)b*m+t)*3+1]=cy;
            nxyz[((size_t)b*m+t)*3+2]=cz;
        }
        __syncthreads();
        float cx=cur[0], cy=cur[1], cz=cur[2];
        float bv=-1e30f; int bj=0x7fffffff;
        #pragma unroll
        for (int i=0;i<PPT;i++){
            int j = tid + i*T;
            if (j < n){
                float dx=px[i]-cx, dy=py[i]-cy, dz=pz[i]-cz;
                float d = fa(fa(fm(dx,dx), fm(dy,dy)), fm(dz,dz));
                float mn = fminf(mind[i], d);
                mind[i] = mn;
                if (mn > bv){ bv=mn; bj=j; }   // ascending j -> lowest index kept on ties
            }
        }
        #pragma unroll
        for (int off=16; off; off>>=1){
            float ov = __shfl_down_sync(0xffffffffu, bv, off);
            int   oj = __shfl_down_sync(0xffffffffu, bj, off);
            if (ov > bv || (ov == bv && oj < bj)){ bv=ov; bj=oj; }
        }
        if ((tid&31)==0){ sv[tid>>5]=bv; si[tid>>5]=bj; }
        __syncthreads();
        if (tid < 32){
            float v = (tid<16)? sv[tid] : -1e30f;
            int   j = (tid<16)? si[tid] : 0x7fffffff;
            #pragma unroll
            for (int off=16; off; off>>=1){
                float ov = __shfl_down_sync(0xffffffffu, v, off);
                int   oj = __shfl_down_sync(0xffffffffu, j, off);
                if (ov > v || (ov == v && oj < j)){ v=ov; j=oj; }
            }
            if (tid==0) slast = j;
        }
        __syncthreads();
        last = slast;
    }
}

// ---------------- ball query: one warp per centroid ----------------
// sorted(where(sqd<=r2, idx, n))[:K] == first K in-ball indices ascending, pad with first.
template<int KS>
__global__ void ball_kernel(const float4* __restrict__ pts, const float* __restrict__ nxyz,
                            int n, int S, float r2, int* __restrict__ out){
    __shared__ int widx[8][KS];
    int w = threadIdx.x >> 5, lane = threadIdx.x & 31;
    int sg = blockIdx.x*8 + w;             // global centroid id = b*S + s
    int b = sg / S;
    const float4* P = pts + (size_t)b*n;
    float cx = nxyz[(size_t)sg*3+0], cy = nxyz[(size_t)sg*3+1], cz = nxyz[(size_t)sg*3+2];
    float sn = fa(fa(fm(cx,cx), fm(cy,cy)), fm(cz,cz));
    int cnt = 0;
    for (int j0=0; j0<n && cnt<KS; j0+=32){
        int j = j0 + lane;
        float4 q = P[j];
        float dot = fa(fa(fm(cx,q.x), fm(cy,q.y)), fm(cz,q.z));
        float sqd = __fsub_rn(fa(sn, q.w), fm(2.0f, dot));
        bool inb = (sqd <= r2);
        unsigned msk = __ballot_sync(0xffffffffu, inb);
        int pos = cnt + __popc(msk & ((1u<<lane)-1u));
        if (inb && pos < KS) widx[w][pos] = j;
        cnt += __popc(msk);
    }
    __syncwarp();
    int c = cnt < KS ? cnt : KS;
    int first = widx[w][0];                 // ball never empty (centroid is a member)
    for (int p = c + lane; p < KS; p += 32) widx[w][p] = first;
    __syncwarp();
    for (int p = lane; p < KS; p += 32) out[(size_t)sg*KS + p] = widx[w][p];
}

// ---------------- group builders ----------------
__global__ void build_g1_kernel(const float* __restrict__ x, const float* __restrict__ nxyz,
                                const int* __restrict__ idx, float* __restrict__ g){
    int r = blockIdx.x*blockDim.x + threadIdx.x;
    if (r >= BB*512*32) return;
    int s = (r>>5) & 511, b = r >> 14;
    int j = idx[r];
    const float* pp = x    + ((size_t)b*NN  + j)*3;
    const float* cc = nxyz + ((size_t)b*512 + s)*3;
    g[(size_t)r*3+0] = pp[0]-cc[0];
    g[(size_t)r*3+1] = pp[1]-cc[1];
    g[(size_t)r*3+2] = pp[2]-cc[2];
}

__global__ void build_g2_kernel(const float* __restrict__ xyz1, const float* __restrict__ feat1,
                                const float* __restrict__ nxyz2, const int* __restrict__ idx,
                                float* __restrict__ g){
    long long e = (long long)blockIdx.x*blockDim.x + threadIdx.x;
    const long long total = (long long)262144*131;
    if (e >= total) return;
    int c = (int)(e % 131);
    int r = (int)(e / 131);
    int s = (r>>6) & 127, b = r >> 13;
    int j = idx[r];
    float v;
    if (c < 3) v = xyz1[((size_t)b*512 + j)*3 + c] - nxyz2[((size_t)b*128 + s)*3 + c];
    else       v = feat1[((size_t)b*512 + j)*128 + (c-3)];
    g[e] = v;
}

__global__ void build_g3_kernel(const float* __restrict__ nxyz2, const float* __restrict__ feat2,
                                float* __restrict__ g){
    int e = blockIdx.x*blockDim.x + threadIdx.x;
    if (e >= 4096*259) return;
    int c = e % 259, r = e / 259;
    float v = (c<3) ? nxyz2[(size_t)r*3+c] : feat2[(size_t)r*256 + (c-3)];
    g[e] = v;
}

// ---------------- max pool over group dim ----------------
__global__ void maxpool_kernel(const float* __restrict__ in, float* __restrict__ out,
                               int G, int Kp, int C){
    int e = blockIdx.x*blockDim.x + threadIdx.x;
    if (e >= G*C) return;
    int g = e / C, c = e % C;
    const float* p = in + (size_t)g*Kp*C + c;
    float v = p[0];
    for (int k=1;k<Kp;k++) v = fmaxf(v, p[(size_t)k*C]);
    out[(size_t)g*C + c] = v;
}

// ---------------- SGEMM: C[M,N] = relu?(A[M,K] * W[N,K]^T + bias) ----------------
// 128x128 tile, BK=8, 256 threads, 8x8 per-thread micro-tile.
__global__ void __launch_bounds__(256)
sgemm_kernel(const float* __restrict__ A, const float* __restrict__ W,
             const float* __restrict__ bias, float* __restrict__ C,
             int M, int N, int K, int doRelu)
{
    __shared__ float As[8][128];
    __shared__ float Ws[8][128];
    int bm = blockIdx.y * 128;
    int bn = blockIdx.x * 128;
    int tid = threadIdx.x;
    int tx = tid & 15, ty = tid >> 4;
    float acc[8][8];
    #pragma unroll
    for (int i=0;i<8;i++)
        #pragma unroll
        for (int j=0;j<8;j++) acc[i][j]=0.f;

    for (int k0=0; k0<K; k0+=8){
        #pragma unroll
        for (int l=0; l<4; l++){
            int t = tid + l*256;
            int r = t >> 3, kk = t & 7;
            int gk = k0 + kk;
            int gm = bm + r;
            As[kk][r] = (gm < M && gk < K) ? A[(size_t)gm*K + gk] : 0.f;
            int gn = bn + r;
            Ws[kk][r] = (gn < N && gk < K) ? W[(size_t)gn*K + gk] : 0.f;
        }
        __syncthreads();
        #pragma unroll
        for (int kk=0; kk<8; kk++){
            float a[8], w[8];
            #pragma unroll
            for (int i=0;i<8;i++) a[i] = As[kk][ty*8+i];
            #pragma unroll
            for (int j=0;j<8;j++) w[j] = Ws[kk][tx*8+j];
            #pragma unroll
            for (int i=0;i<8;i++)
                #pragma unroll
                for (int j=0;j<8;j++)
                    acc[i][j] = fmaf(a[i], w[j], acc[i][j]);
        }
        __syncthreads();
    }
    #pragma unroll
    for (int i=0;i<8;i++){
        int gm = bm + ty*8 + i;
        if (gm >= M) continue;
        #pragma unroll
        for (int j=0;j<8;j++){
            int gn = bn + tx*8 + j;
            if (gn >= N) continue;
            float v = acc[i][j] + bias[gn];
            if (doRelu) v = fmaxf(v, 0.f);
            C[(size_t)gm*N + gn] = v;
        }
    }
}

// ---------------- softmax over 40 classes, 32 rows ----------------
__global__ void softmax_kernel(const float* __restrict__ in, float* __restrict__ out){
    int b = threadIdx.y;
    int lane = threadIdx.x;
    float v0 = in[b*40 + lane];
    float v1 = (lane < 8) ? in[b*40 + lane + 32] : -INFINITY;
    float mx = fmaxf(v0, v1);
    #pragma unroll
    for (int off=16; off; off>>=1) mx = fmaxf(mx, __shfl_xor_sync(0xffffffffu, mx, off));
    float e0 = expf(v0 - mx);
    float e1 = (lane < 8) ? expf(v1 - mx) : 0.f;
    float sm = e0 + e1;
    #pragma unroll
    for (int off=16; off; off>>=1) sm += __shfl_xor_sync(0xffffffffu, sm, off);
    out[b*40 + lane] = e0 / sm;
    if (lane < 8) out[b*40 + lane + 32] = e1 / sm;
}

// ---------------- host launcher ----------------
extern "C" void kernel_launch(void* const* d_in, const int* in_sizes, int n_in,
                              void* d_out, int out_size)
{
    (void)in_sizes; (void)n_in; (void)out_size;
    const float* x    = (const float*)d_in[0];
    const float* w1[3]= {(const float*)d_in[1],(const float*)d_in[3],(const float*)d_in[5]};
    const float* b1[3]= {(const float*)d_in[2],(const float*)d_in[4],(const float*)d_in[6]};
    const float* w2[3]= {(const float*)d_in[7],(const float*)d_in[9],(const float*)d_in[11]};
    const float* b2[3]= {(const float*)d_in[8],(const float*)d_in[10],(const float*)d_in[12]};
    const float* w3[3]= {(const float*)d_in[13],(const float*)d_in[15],(const float*)d_in[17]};
    const float* b3[3]= {(const float*)d_in[14],(const float*)d_in[16],(const float*)d_in[18]};
    const float* fc1w=(const float*)d_in[19]; const float* fc1b=(const float*)d_in[20];
    const float* fc2w=(const float*)d_in[21]; const float* fc2b=(const float*)d_in[22];
    const float* fc3w=(const float*)d_in[23]; const float* fc3b=(const float*)d_in[24];

    float4 *pts1, *pts2;
    int *fidx1, *fidx2, *idx1, *idx2;
    float *nxyz1, *nxyz2, *feat1, *feat2, *feat3, *fc1o, *fc2o, *logits, *bufA, *bufB;
    cudaGetSymbolAddress((void**)&pts1,  g_pts1);
    cudaGetSymbolAddress((void**)&pts2,  g_pts2);
    cudaGetSymbolAddress((void**)&fidx1, g_fidx1);
    cudaGetSymbolAddress((void**)&nxyz1, g_nxyz1);
    cudaGetSymbolAddress((void**)&idx1,  g_idx1);
    cudaGetSymbolAddress((void**)&fidx2, g_fidx2);
    cudaGetSymbolAddress((void**)&nxyz2, g_nxyz2);
    cudaGetSymbolAddress((void**)&idx2,  g_idx2);
    cudaGetSymbolAddress((void**)&feat1, g_feat1);
    cudaGetSymbolAddress((void**)&feat2, g_feat2);
    cudaGetSymbolAddress((void**)&feat3, g_feat3);
    cudaGetSymbolAddress((void**)&fc1o,  g_fc1o);
    cudaGetSymbolAddress((void**)&fc2o,  g_fc2o);
    cudaGetSymbolAddress((void**)&logits,g_logits);
    cudaGetSymbolAddress((void**)&bufA,  g_bufA);
    cudaGetSymbolAddress((void**)&bufB,  g_bufB);

    // ---- SA1: npoint=512, r=0.2, K=32, MLP 3->64->64->128 ----
    prep_pts_kernel<<<(BB*NN+255)/256, 256>>>(x, pts1, BB*NN);
    fps_kernel<8><<<BB, 512>>>(x, NN, 512, fidx1, nxyz1);
    ball_kernel<32><<<(BB*512)/8, 256>>>(pts1, nxyz1, NN, 512, 0.04f, idx1);
    build_g1_kernel<<<(BB*512*32+255)/256, 256>>>(x, nxyz1, idx1, bufA);
    sgemm_kernel<<<dim3(1,4096), 256>>>(bufA, w1[0], b1[0], bufB, 524288,  64,   3, 1);
    sgemm_kernel<<<dim3(1,4096), 256>>>(bufB, w1[1], b1[1], bufA, 524288,  64,  64, 1);
    sgemm_kernel<<<dim3(1,4096), 256>>>(bufA, w1[2], b1[2], bufB, 524288, 128,  64, 1);
    maxpool_kernel<<<(16384*128+255)/256, 256>>>(bufB, feat1, 16384, 32, 128);

    // ---- SA2: npoint=128, r=0.4, K=64, MLP 131->128->128->256 ----
    prep_pts_kernel<<<(BB*512+255)/256, 256>>>(nxyz1, pts2, BB*512);
    fps_kernel<1><<<BB, 512>>>(nxyz1, 512, 128, fidx2, nxyz2);
    ball_kernel<64><<<(BB*128)/8, 256>>>(pts2, nxyz2, 512, 128, 0.16f, idx2);
    {
        long long total = (long long)262144*131;
        int blocks = (int)((total + 255)/256);
        build_g2_kernel<<<blocks, 256>>>(nxyz1, feat1, nxyz2, idx2, bufA);
    }
    sgemm_kernel<<<dim3(1,2048), 256>>>(bufA, w2[0], b2[0], bufB, 262144, 128, 131, 1);
    sgemm_kernel<<<dim3(1,2048), 256>>>(bufB, w2[1], b2[1], bufA, 262144, 128, 128, 1);
    sgemm_kernel<<<dim3(2,2048), 256>>>(bufA, w2[2], b2[2], bufB, 262144, 256, 128, 1);
    maxpool_kernel<<<(4096*256+255)/256, 256>>>(bufB, feat2, 4096, 64, 256);

    // ---- SA3 (group all): MLP 259->256->512->1024, max over 128 ----
    build_g3_kernel<<<(4096*259+255)/256, 256>>>(nxyz2, feat2, bufA);
    sgemm_kernel<<<dim3(2,32), 256>>>(bufA, w3[0], b3[0], bufB, 4096,  256, 259, 1);
    sgemm_kernel<<<dim3(4,32), 256>>>(bufB, w3[1], b3[1], bufA, 4096,  512, 256, 1);
    sgemm_kernel<<<dim3(8,32), 256>>>(bufA, w3[2], b3[2], bufB, 4096, 1024, 512, 1);
    maxpool_kernel<<<(32*1024+255)/256, 256>>>(bufB, feat3, 32, 128, 1024);

    // ---- FC head + softmax ----
    sgemm_kernel<<<dim3(4,1), 256>>>(feat3, fc1w, fc1b, fc1o,  32, 512, 1024, 1);
    sgemm_kernel<<<dim3(2,1), 256>>>(fc1o,  fc2w, fc2b, fc2o,  32, 256,  512, 1);
    sgemm_kernel<<<dim3(1,1), 256>>>(fc2o,  fc3w, fc3b, logits,32,  40,  256, 0);
    softmax_kernel<<<1, dim3(32,32)>>>(logits, (float*)d_out);
}